// round 1
// baseline (speedup 1.0000x reference)
#include <cuda_runtime.h>
#include <math.h>

// Problem constants
#define LL 1024
#define BB 2
#define FF 1024
#define HH 2048
#define NN 16
#define RR 64
#define KK 4
#define MROWS (LL*BB)        // 2048 rows = (l,b) flattened
#define PROJC (RR + 2*NN)    // 96

// ---------------- scratch (device globals: allocation-free) ----------------
__device__ float g_h[(size_t)MROWS * (2*HH)];   // 2048 x 4096  (xs | res)  32MB
__device__ float g_u[(size_t)MROWS * HH];       // 2048 x 2048  silu(conv)  16MB
__device__ float g_proj[(size_t)MROWS * PROJC]; // 2048 x 96
__device__ float g_delta[(size_t)MROWS * HH];   // 2048 x 2048              16MB
__device__ float g_z[(size_t)MROWS * HH];       // 2048 x 2048 y*silu(res)  16MB

// ---------------- tiled fp32 GEMM: 128x128x16, 256 thr, 8x8/thread --------
#define BM 128
#define BN 128
#define BK 16

__device__ __forceinline__ float sigmoid_f(float x) {
    return 1.f / (1.f + __expf(-x));
}

// EPI: 0 = plain store, 1 = softplus(acc + bias[col])
template<int EPI>
__global__ __launch_bounds__(256, 2)
void gemm_k(const float* __restrict__ A, int lda,
            const float* __restrict__ B, int ldb,
            float* __restrict__ C, int ldc,
            int Nn, int Kk, const float* __restrict__ bias)
{
    __shared__ float As[BK][BM + 1];   // +1 pad: conflict-free transposed stores
    __shared__ float Bs[BK][BN];

    const int tid  = threadIdx.x;
    const int row0 = blockIdx.y * BM;
    const int col0 = blockIdx.x * BN;
    const int tx = tid & 15;
    const int ty = tid >> 4;

    float acc[8][8];
#pragma unroll
    for (int i = 0; i < 8; i++)
#pragma unroll
        for (int j = 0; j < 8; j++) acc[i][j] = 0.f;

    for (int kt = 0; kt < Kk; kt += BK) {
        // A tile: 128x16, float4 along K, stored transposed As[k][m]
#pragma unroll
        for (int i = 0; i < 2; i++) {
            int s  = tid + i * 256;          // 0..511
            int m  = s >> 2;                 // 0..127
            int kq = (s & 3) << 2;           // 0,4,8,12
            float4 v = *reinterpret_cast<const float4*>(
                &A[(size_t)(row0 + m) * lda + kt + kq]);
            As[kq + 0][m] = v.x; As[kq + 1][m] = v.y;
            As[kq + 2][m] = v.z; As[kq + 3][m] = v.w;
        }
        // B tile: 16x128, float4 along N, guard N (for Nn=96 case)
#pragma unroll
        for (int i = 0; i < 2; i++) {
            int s   = tid + i * 256;         // 0..511
            int kk  = s >> 5;                // 0..15
            int col = (s & 31) << 2;         // 0..124
            float4 v = make_float4(0.f, 0.f, 0.f, 0.f);
            if (col0 + col < Nn)
                v = *reinterpret_cast<const float4*>(
                    &B[(size_t)(kt + kk) * ldb + col0 + col]);
            *reinterpret_cast<float4*>(&Bs[kk][col]) = v;
        }
        __syncthreads();

#pragma unroll
        for (int k = 0; k < BK; k++) {
            float a[8], b[8];
#pragma unroll
            for (int i = 0; i < 8; i++) a[i] = As[k][ty * 8 + i];
#pragma unroll
            for (int j = 0; j < 8; j++) b[j] = Bs[k][tx * 8 + j];
#pragma unroll
            for (int i = 0; i < 8; i++)
#pragma unroll
                for (int j = 0; j < 8; j++)
                    acc[i][j] = fmaf(a[i], b[j], acc[i][j]);
        }
        __syncthreads();
    }

#pragma unroll
    for (int i = 0; i < 8; i++) {
        int r = row0 + ty * 8 + i;
#pragma unroll
        for (int j = 0; j < 8; j++) {
            int c = col0 + tx * 8 + j;
            if (c < Nn) {
                float v = acc[i][j];
                if (EPI == 1) {
                    v += bias[c];
                    v = (v > 20.f) ? v : log1pf(expf(v));
                }
                C[(size_t)r * ldc + c] = v;
            }
        }
    }
}

// ---------------- causal grouped conv (K=4, 2 groups) as shifted GEMM -----
// out[r, co] = sum_{k=0..3} sum_{ci} h[r - 2*(3-k), g*1024+ci] * Wc[k*1024+ci, co]
// fused epilogue: u = silu(out + b_conv)
__global__ __launch_bounds__(256, 2)
void conv_silu_k(const float* __restrict__ h, const float* __restrict__ Wc,
                 const float* __restrict__ bconv, float* __restrict__ U)
{
    __shared__ float As[BK][BM + 1];
    __shared__ float Bs[BK][BN];

    const int tid  = threadIdx.x;
    const int row0 = blockIdx.y * BM;
    const int col0 = blockIdx.x * BN;
    const int grp  = col0 >> 10;     // output group (0/1); BN=128 divides 1024
    const int tx = tid & 15;
    const int ty = tid >> 4;

    float acc[8][8];
#pragma unroll
    for (int i = 0; i < 8; i++)
#pragma unroll
        for (int j = 0; j < 8; j++) acc[i][j] = 0.f;

    for (int kt = 0; kt < KK * 1024; kt += BK) {
        const int k     = kt >> 10;        // conv tap, constant within tile
        const int ci0   = kt & 1023;
        const int shift = 2 * (3 - k);     // row shift in (t,b) space
#pragma unroll
        for (int i = 0; i < 2; i++) {
            int s  = tid + i * 256;
            int m  = s >> 2;
            int kq = (s & 3) << 2;
            int rs = row0 + m - shift;
            float4 v = make_float4(0.f, 0.f, 0.f, 0.f);
            if (rs >= 0)
                v = *reinterpret_cast<const float4*>(
                    &h[(size_t)rs * (2 * HH) + grp * 1024 + ci0 + kq]);
            As[kq + 0][m] = v.x; As[kq + 1][m] = v.y;
            As[kq + 2][m] = v.z; As[kq + 3][m] = v.w;
        }
#pragma unroll
        for (int i = 0; i < 2; i++) {
            int s   = tid + i * 256;
            int kk  = s >> 5;
            int col = (s & 31) << 2;
            float4 v = *reinterpret_cast<const float4*>(
                &Wc[(size_t)(kt + kk) * HH + col0 + col]);
            *reinterpret_cast<float4*>(&Bs[kk][col]) = v;
        }
        __syncthreads();

#pragma unroll
        for (int k2 = 0; k2 < BK; k2++) {
            float a[8], b[8];
#pragma unroll
            for (int i = 0; i < 8; i++) a[i] = As[k2][ty * 8 + i];
#pragma unroll
            for (int j = 0; j < 8; j++) b[j] = Bs[k2][tx * 8 + j];
#pragma unroll
            for (int i = 0; i < 8; i++)
#pragma unroll
                for (int j = 0; j < 8; j++)
                    acc[i][j] = fmaf(a[i], b[j], acc[i][j]);
        }
        __syncthreads();
    }

#pragma unroll
    for (int i = 0; i < 8; i++) {
        int r = row0 + ty * 8 + i;
#pragma unroll
        for (int j = 0; j < 8; j++) {
            int c = col0 + tx * 8 + j;
            float v = acc[i][j] + bconv[c];
            U[(size_t)r * HH + c] = v * sigmoid_f(v);   // silu
        }
    }
}

// ---------------- selective scan + fused z = y * silu(res) ----------------
// 16 lanes per (b,h) chain; lane n owns state n. 2 chains per warp.
__global__ __launch_bounds__(256)
void scan_k(const float* __restrict__ delta, const float* __restrict__ u,
            const float* __restrict__ proj, const float* __restrict__ A_log,
            const float* __restrict__ D, const float* __restrict__ h,
            float* __restrict__ z)
{
    const int gtid = blockIdx.x * blockDim.x + threadIdx.x;
    const int warp = gtid >> 5;
    const int lane = threadIdx.x & 31;
    const int sub  = lane >> 4;          // chain within warp
    const int n    = lane & 15;          // state index
    const int c    = warp * 2 + sub;     // 0..4095
    const int hi   = c >> 1;             // head 0..2047
    const int b    = c & 1;              // batch

    const float A  = -expf(A_log[hi * NN + n]);
    const float Dh = D[hi];
    float s = 0.f;

    for (int t = 0; t < LL; t++) {
        const int r = t * BB + b;
        float dt = delta[(size_t)r * HH + hi];
        dt = fminf(fmaxf(dt, 0.001f), 0.1f);
        const float uu = u[(size_t)r * HH + hi];
        const float Bn = proj[(size_t)r * PROJC + n];
        const float Cn = proj[(size_t)r * PROJC + NN + n];

        s = __expf(dt * A) * s + (dt * uu) * Bn;

        float p = Cn * s;
        p += __shfl_xor_sync(0xffffffffu, p, 1);
        p += __shfl_xor_sync(0xffffffffu, p, 2);
        p += __shfl_xor_sync(0xffffffffu, p, 4);
        p += __shfl_xor_sync(0xffffffffu, p, 8);

        if (n == 0) {
            const float yv  = p + uu * Dh;
            const float res = h[(size_t)r * (2 * HH) + HH + hi];
            z[(size_t)r * HH + hi] = yv * (res * sigmoid_f(res));
        }
    }
}

// ---------------- launch ---------------------------------------------------
extern "C" void kernel_launch(void* const* d_in, const int* in_sizes, int n_in,
                              void* d_out, int out_size)
{
    const float* x      = (const float*)d_in[0];
    const float* W_in   = (const float*)d_in[1];
    const float* W_conv = (const float*)d_in[2];
    const float* b_conv = (const float*)d_in[3];
    const float* A_log  = (const float*)d_in[4];
    const float* D      = (const float*)d_in[5];
    const float* W_ssm  = (const float*)d_in[6];
    const float* W_dt   = (const float*)d_in[7];
    const float* b_dt   = (const float*)d_in[8];
    const float* W_out  = (const float*)d_in[9];
    float* out = (float*)d_out;

    void* p;
    cudaGetSymbolAddress(&p, g_h);     float* hbuf  = (float*)p;
    cudaGetSymbolAddress(&p, g_u);     float* ubuf  = (float*)p;
    cudaGetSymbolAddress(&p, g_proj);  float* pbuf  = (float*)p;
    cudaGetSymbolAddress(&p, g_delta); float* dbuf  = (float*)p;
    cudaGetSymbolAddress(&p, g_z);     float* zbuf  = (float*)p;

    dim3 blk(256);

    // 1) h = x @ W_in : (2048,1024)@(1024,4096)
    gemm_k<0><<<dim3(2 * HH / BN, MROWS / BM), blk>>>(
        x, FF, W_in, 2 * HH, hbuf, 2 * HH, 2 * HH, FF, nullptr);

    // 2) u = silu(causal grouped conv(xs) + b_conv)
    conv_silu_k<<<dim3(HH / BN, MROWS / BM), blk>>>(hbuf, W_conv, b_conv, ubuf);

    // 3) proj = u @ W_ssm : (2048,2048)@(2048,96)
    gemm_k<0><<<dim3(1, MROWS / BM), blk>>>(
        ubuf, HH, W_ssm, PROJC, pbuf, PROJC, PROJC, HH, nullptr);

    // 4) delta = softplus(proj[:,32:96] @ W_dt + b_dt) : (2048,64)@(64,2048)
    gemm_k<1><<<dim3(HH / BN, MROWS / BM), blk>>>(
        pbuf + 2 * NN, PROJC, W_dt, HH, dbuf, HH, HH, RR, b_dt);

    // 5) selective scan + z = y * silu(res): 4096 chains * 16 lanes
    scan_k<<<BB * HH * NN / 256, blk>>>(dbuf, ubuf, pbuf, A_log, D, hbuf, zbuf);

    // 6) out = z @ W_out : (2048,2048)@(2048,1024)
    gemm_k<0><<<dim3(FF / BN, MROWS / BM), blk>>>(
        zbuf, HH, W_out, FF, out, FF, FF, HH, nullptr);
}

// round 3
// speedup vs baseline: 1.0693x; 1.0693x over previous
#include <cuda_runtime.h>
#include <cstdint>
#include <math.h>

// Problem constants
#define LL 1024
#define BB 2
#define FF 1024
#define HH 2048
#define NN 16
#define RR 64
#define KK 4
#define MROWS (LL*BB)        // 2048 rows = (l,b) flattened
#define PROJC (RR + 2*NN)    // 96

// ---------------- scratch (device globals: allocation-free) ----------------
__device__ float g_h[(size_t)MROWS * (2*HH)];   // 2048 x 4096  (xs | res)
__device__ float g_u[(size_t)MROWS * HH];       // 2048 x 2048  silu(conv)
__device__ float g_proj[(size_t)MROWS * PROJC]; // 2048 x 96
__device__ float g_delta[(size_t)MROWS * HH];   // 2048 x 2048
__device__ float g_z[(size_t)MROWS * HH];       // 2048 x 2048  y*silu(res)

#define BM 128
#define BN 128
#define BK 16

__device__ __forceinline__ float sigmoid_f(float x) {
    return 1.f / (1.f + __expf(-x));
}

// 16B async copy, zero-fill when invalid (no read issued when src_size==0)
__device__ __forceinline__ void cp16(float* smem_dst, const float* gsrc, bool valid) {
    unsigned int s = (unsigned int)__cvta_generic_to_shared(smem_dst);
    int sz = valid ? 16 : 0;
    asm volatile("cp.async.cg.shared.global [%0], [%1], 16, %2;\n"
                 :: "r"(s), "l"(gsrc), "r"(sz));
}
#define CP_COMMIT() asm volatile("cp.async.commit_group;\n")
#define CP_WAIT0()  asm volatile("cp.async.wait_group 0;\n")

// ---------------- pipelined fp32 GEMM: 128x128x16, 256 thr, 8x8/thread ----
// EPI: 0 = plain store, 1 = softplus(acc + bias[col])
template<int EPI>
__global__ __launch_bounds__(256, 2)
void gemm_k(const float* __restrict__ A, int lda,
            const float* __restrict__ B, int ldb,
            float* __restrict__ C, int ldc,
            int Nn, int Kk, const float* __restrict__ bias)
{
    __shared__ float As[2][BK][BM + 4];   // transposed A tiles (pad keeps 16B align)
    __shared__ float Bs[2][BK][BN];

    const int tid  = threadIdx.x;
    const int row0 = blockIdx.y * BM;
    const int col0 = blockIdx.x * BN;
    const int tx = tid & 15;
    const int ty = tid >> 4;

    float4 ra[2];

    auto ldA = [&](int kt) {
#pragma unroll
        for (int i = 0; i < 2; i++) {
            int s = tid + i * 256, m = s >> 2, kq = (s & 3) << 2;
            ra[i] = *reinterpret_cast<const float4*>(
                &A[(size_t)(row0 + m) * lda + kt + kq]);
        }
    };
    auto stA = [&](int buf) {
#pragma unroll
        for (int i = 0; i < 2; i++) {
            int s = tid + i * 256, m = s >> 2, kq = (s & 3) << 2;
            As[buf][kq + 0][m] = ra[i].x; As[buf][kq + 1][m] = ra[i].y;
            As[buf][kq + 2][m] = ra[i].z; As[buf][kq + 3][m] = ra[i].w;
        }
    };
    auto ldB = [&](int kt, int buf) {
#pragma unroll
        for (int i = 0; i < 2; i++) {
            int s = tid + i * 256, kk = s >> 5, col = (s & 31) << 2;
            cp16(&Bs[buf][kk][col], &B[(size_t)(kt + kk) * ldb + col0 + col],
                 col0 + col < Nn);
        }
        CP_COMMIT();
    };

    float acc[8][8];
#pragma unroll
    for (int i = 0; i < 8; i++)
#pragma unroll
        for (int j = 0; j < 8; j++) acc[i][j] = 0.f;

    // prologue: tile 0 into buffer 0
    ldA(0); ldB(0, 0); stA(0);
    CP_WAIT0();
    __syncthreads();

    const int T = Kk / BK;
    for (int t = 0; t < T; t++) {
        const int buf = t & 1;
        if (t + 1 < T) { ldA((t + 1) * BK); ldB((t + 1) * BK, buf ^ 1); }

#pragma unroll
        for (int k = 0; k < BK; k++) {
            float a[8], b[8];
            *(float4*)&a[0] = *(const float4*)&As[buf][k][ty * 8];
            *(float4*)&a[4] = *(const float4*)&As[buf][k][ty * 8 + 4];
            *(float4*)&b[0] = *(const float4*)&Bs[buf][k][tx * 8];
            *(float4*)&b[4] = *(const float4*)&Bs[buf][k][tx * 8 + 4];
#pragma unroll
            for (int i = 0; i < 8; i++)
#pragma unroll
                for (int j = 0; j < 8; j++)
                    acc[i][j] = fmaf(a[i], b[j], acc[i][j]);
        }

        if (t + 1 < T) {
            stA(buf ^ 1);
            CP_WAIT0();
            __syncthreads();
        }
    }

#pragma unroll
    for (int i = 0; i < 8; i++) {
        int r = row0 + ty * 8 + i;
#pragma unroll
        for (int j = 0; j < 8; j++) {
            int c = col0 + tx * 8 + j;
            if (c < Nn) {
                float v = acc[i][j];
                if (EPI == 1) {
                    v += bias[c];
                    v = (v > 20.f) ? v : log1pf(expf(v));
                }
                C[(size_t)r * ldc + c] = v;
            }
        }
    }
}

// ---------------- causal grouped conv (K=4, 2 groups) as shifted GEMM -----
// out[r, co] = sum_k sum_ci h[r - 2*(3-k), g*1024+ci] * Wc[(k*1024+ci), co]
// fused epilogue: u = silu(out + b_conv)
__global__ __launch_bounds__(256, 2)
void conv_silu_k(const float* __restrict__ h, const float* __restrict__ Wc,
                 const float* __restrict__ bconv, float* __restrict__ U)
{
    __shared__ float As[2][BK][BM + 4];
    __shared__ float Bs[2][BK][BN];

    const int tid  = threadIdx.x;
    const int row0 = blockIdx.y * BM;
    const int col0 = blockIdx.x * BN;
    const int grp  = col0 >> 10;          // output group (0/1); BN divides 1024
    const int tx = tid & 15;
    const int ty = tid >> 4;

    float4 ra[2];

    auto ldA = [&](int kt) {
        const int k     = kt >> 10;
        const int ci0   = kt & 1023;
        const int shift = 2 * (3 - k);
#pragma unroll
        for (int i = 0; i < 2; i++) {
            int s = tid + i * 256, m = s >> 2, kq = (s & 3) << 2;
            int rs = row0 + m - shift;
            float4 v = make_float4(0.f, 0.f, 0.f, 0.f);
            if (rs >= 0)
                v = *reinterpret_cast<const float4*>(
                    &h[(size_t)rs * (2 * HH) + grp * 1024 + ci0 + kq]);
            ra[i] = v;
        }
    };
    auto stA = [&](int buf) {
#pragma unroll
        for (int i = 0; i < 2; i++) {
            int s = tid + i * 256, m = s >> 2, kq = (s & 3) << 2;
            As[buf][kq + 0][m] = ra[i].x; As[buf][kq + 1][m] = ra[i].y;
            As[buf][kq + 2][m] = ra[i].z; As[buf][kq + 3][m] = ra[i].w;
        }
    };
    auto ldB = [&](int kt, int buf) {
#pragma unroll
        for (int i = 0; i < 2; i++) {
            int s = tid + i * 256, kk = s >> 5, col = (s & 31) << 2;
            cp16(&Bs[buf][kk][col], &Wc[(size_t)(kt + kk) * HH + col0 + col], true);
        }
        CP_COMMIT();
    };

    float acc[8][8];
#pragma unroll
    for (int i = 0; i < 8; i++)
#pragma unroll
        for (int j = 0; j < 8; j++) acc[i][j] = 0.f;

    ldA(0); ldB(0, 0); stA(0);
    CP_WAIT0();
    __syncthreads();

    const int T = (KK * 1024) / BK;
    for (int t = 0; t < T; t++) {
        const int buf = t & 1;
        if (t + 1 < T) { ldA((t + 1) * BK); ldB((t + 1) * BK, buf ^ 1); }

#pragma unroll
        for (int k2 = 0; k2 < BK; k2++) {
            float a[8], b[8];
            *(float4*)&a[0] = *(const float4*)&As[buf][k2][ty * 8];
            *(float4*)&a[4] = *(const float4*)&As[buf][k2][ty * 8 + 4];
            *(float4*)&b[0] = *(const float4*)&Bs[buf][k2][tx * 8];
            *(float4*)&b[4] = *(const float4*)&Bs[buf][k2][tx * 8 + 4];
#pragma unroll
            for (int i = 0; i < 8; i++)
#pragma unroll
                for (int j = 0; j < 8; j++)
                    acc[i][j] = fmaf(a[i], b[j], acc[i][j]);
        }

        if (t + 1 < T) {
            stA(buf ^ 1);
            CP_WAIT0();
            __syncthreads();
        }
    }

#pragma unroll
    for (int i = 0; i < 8; i++) {
        int r = row0 + ty * 8 + i;
#pragma unroll
        for (int j = 0; j < 8; j++) {
            int c = col0 + tx * 8 + j;
            float v = acc[i][j] + bconv[c];
            U[(size_t)r * HH + c] = v * sigmoid_f(v);   // silu
        }
    }
}

// ---------------- selective scan + fused z = y * silu(res) ----------------
// 16 lanes per (b,h) chain; lane n owns state n. 2 chains per warp.
__global__ __launch_bounds__(256)
void scan_k(const float* __restrict__ delta, const float* __restrict__ u,
            const float* __restrict__ proj, const float* __restrict__ A_log,
            const float* __restrict__ D, const float* __restrict__ h,
            float* __restrict__ z)
{
    const int gtid = blockIdx.x * blockDim.x + threadIdx.x;
    const int warp = gtid >> 5;
    const int lane = threadIdx.x & 31;
    const int sub  = lane >> 4;          // chain within warp
    const int n    = lane & 15;          // state index
    const int c    = warp * 2 + sub;     // 0..4095
    const int hi   = c >> 1;             // head 0..2047
    const int b    = c & 1;              // batch

    const float A  = -expf(A_log[hi * NN + n]);
    const float Dh = D[hi];
    float s = 0.f;

    for (int t = 0; t < LL; t++) {
        const int r = t * BB + b;
        float dt = __ldg(&delta[(size_t)r * HH + hi]);
        dt = fminf(fmaxf(dt, 0.001f), 0.1f);
        const float uu = __ldg(&u[(size_t)r * HH + hi]);
        const float Bn = __ldg(&proj[(size_t)r * PROJC + n]);
        const float Cn = __ldg(&proj[(size_t)r * PROJC + NN + n]);

        s = __expf(dt * A) * s + (dt * uu) * Bn;

        float p = Cn * s;
        p += __shfl_xor_sync(0xffffffffu, p, 1);
        p += __shfl_xor_sync(0xffffffffu, p, 2);
        p += __shfl_xor_sync(0xffffffffu, p, 4);
        p += __shfl_xor_sync(0xffffffffu, p, 8);

        if (n == 0) {
            const float yv  = p + uu * Dh;
            const float res = __ldg(&h[(size_t)r * (2 * HH) + HH + hi]);
            z[(size_t)r * HH + hi] = yv * (res * sigmoid_f(res));
        }
    }
}

// ---------------- launch ---------------------------------------------------
extern "C" void kernel_launch(void* const* d_in, const int* in_sizes, int n_in,
                              void* d_out, int out_size)
{
    const float* x      = (const float*)d_in[0];
    const float* W_in   = (const float*)d_in[1];
    const float* W_conv = (const float*)d_in[2];
    const float* b_conv = (const float*)d_in[3];
    const float* A_log  = (const float*)d_in[4];
    const float* D      = (const float*)d_in[5];
    const float* W_ssm  = (const float*)d_in[6];
    const float* W_dt   = (const float*)d_in[7];
    const float* b_dt   = (const float*)d_in[8];
    const float* W_out  = (const float*)d_in[9];
    float* out = (float*)d_out;

    void* p;
    cudaGetSymbolAddress(&p, g_h);     float* hbuf  = (float*)p;
    cudaGetSymbolAddress(&p, g_u);     float* ubuf  = (float*)p;
    cudaGetSymbolAddress(&p, g_proj);  float* pbuf  = (float*)p;
    cudaGetSymbolAddress(&p, g_delta); float* dbuf  = (float*)p;
    cudaGetSymbolAddress(&p, g_z);     float* zbuf  = (float*)p;

    dim3 blk(256);

    // 1) h = x @ W_in : (2048,1024)@(1024,4096)
    gemm_k<0><<<dim3(2 * HH / BN, MROWS / BM), blk>>>(
        x, FF, W_in, 2 * HH, hbuf, 2 * HH, 2 * HH, FF, nullptr);

    // 2) u = silu(causal grouped conv(xs) + b_conv)
    conv_silu_k<<<dim3(HH / BN, MROWS / BM), blk>>>(hbuf, W_conv, b_conv, ubuf);

    // 3) proj = u @ W_ssm : (2048,2048)@(2048,96)
    gemm_k<0><<<dim3(1, MROWS / BM), blk>>>(
        ubuf, HH, W_ssm, PROJC, pbuf, PROJC, PROJC, HH, nullptr);

    // 4) delta = softplus(proj[:,32:96] @ W_dt + b_dt) : (2048,64)@(64,2048)
    gemm_k<1><<<dim3(HH / BN, MROWS / BM), blk>>>(
        pbuf + 2 * NN, PROJC, W_dt, HH, dbuf, HH, HH, RR, b_dt);

    // 5) selective scan + z = y * silu(res): 4096 chains * 16 lanes
    scan_k<<<BB * HH * NN / 256, blk>>>(dbuf, ubuf, pbuf, A_log, D, hbuf, zbuf);

    // 6) out = z @ W_out : (2048,2048)@(2048,1024)
    gemm_k<0><<<dim3(FF / BN, MROWS / BM), blk>>>(
        zbuf, HH, W_out, FF, out, FF, FF, HH, nullptr);
}

// round 4
// speedup vs baseline: 1.7282x; 1.6163x over previous
#include <cuda_runtime.h>
#include <cstdint>
#include <math.h>

// Problem constants
#define LL 1024
#define BB 2
#define FF 1024
#define HH 2048
#define NN 16
#define RR 64
#define KK 4
#define MROWS (LL*BB)        // 2048 rows = (l,b) flattened
#define PROJC (RR + 2*NN)    // 96

// ---------------- scratch (device globals: allocation-free) ----------------
__device__ float g_h[(size_t)MROWS * (2*HH)];   // 2048 x 4096  (xs | res)
__device__ float g_u[(size_t)MROWS * HH];       // 2048 x 2048
__device__ float g_proj[(size_t)MROWS * PROJC]; // 2048 x 96
__device__ float g_delta[(size_t)MROWS * HH];   // 2048 x 2048
__device__ float g_z[(size_t)MROWS * HH];       // 2048 x 2048

#define BM 128
#define BN 128
#define BK 16
#define AS_S 20    // As row stride (words): banks spread 20m%32 = {0,20,8,28,...}
#define BS_S 136   // Bs row stride (words): (8k+n)%32 conflict-free frag loads

__device__ __forceinline__ float sigmoid_f(float x) {
    return 1.f / (1.f + __expf(-x));
}

__device__ __forceinline__ unsigned tf32_of(float f) {
    unsigned u;
    asm("cvt.rna.tf32.f32 %0, %1;" : "=r"(u) : "f"(f));
    return u;
}

__device__ __forceinline__ void mma_tf32(float* d, const unsigned* a, const unsigned* b) {
    asm volatile(
        "mma.sync.aligned.m16n8k8.row.col.f32.tf32.tf32.f32 "
        "{%0,%1,%2,%3}, {%4,%5,%6,%7}, {%8,%9}, {%0,%1,%2,%3};\n"
        : "+f"(d[0]), "+f"(d[1]), "+f"(d[2]), "+f"(d[3])
        : "r"(a[0]), "r"(a[1]), "r"(a[2]), "r"(a[3]), "r"(b[0]), "r"(b[1]));
}

// 16B async copy; src_size 0 => zero-fill, no read
__device__ __forceinline__ void cp16(float* smem_dst, const float* gsrc, bool valid) {
    unsigned int s = (unsigned int)__cvta_generic_to_shared(smem_dst);
    int sz = valid ? 16 : 0;
    asm volatile("cp.async.cg.shared.global [%0], [%1], 16, %2;\n"
                 :: "r"(s), "l"(gsrc), "r"(sz));
}
#define CP_COMMIT() asm volatile("cp.async.commit_group;\n")
#define CP_WAIT0()  asm volatile("cp.async.wait_group 0;\n")

// ================= TF32 tensor-core GEMM, 128x128xK, 256 thr ==============
// EPI: 0 = plain store, 1 = softplus(acc + bias[col])
template<int EPI>
__global__ __launch_bounds__(256, 2)
void gemm_k(const float* __restrict__ A, int lda,
            const float* __restrict__ B, int ldb,
            float* __restrict__ C, int ldc,
            int Nn, int Kk, const float* __restrict__ bias)
{
    __shared__ float As[2][BM][AS_S];
    __shared__ float Bs[2][BK][BS_S];

    const int tid  = threadIdx.x;
    const int row0 = blockIdx.y * BM;
    const int col0 = blockIdx.x * BN;
    const int warp = tid >> 5;
    const int lane = tid & 31;
    const int gid  = lane >> 2;        // 0..7
    const int tig  = lane & 3;         // 0..3
    const int wm0  = (warp & 3) * 32;  // warp m origin in tile
    const int wn0  = (warp >> 2) * 64; // warp n origin in tile

    auto ld_tile = [&](int kt, int buf) {
        // A: 128 rows x 16 floats = 512 x 16B segs, 2/thread
#pragma unroll
        for (int i = 0; i < 2; i++) {
            int s = tid + i * 256, m = s >> 2, j = (s & 3) << 2;
            cp16(&As[buf][m][j], &A[(size_t)(row0 + m) * lda + kt + j], true);
        }
        // B: 16 rows x 128 floats = 512 x 16B segs, 2/thread
#pragma unroll
        for (int i = 0; i < 2; i++) {
            int s = tid + i * 256, kk = s >> 5, col = (s & 31) << 2;
            cp16(&Bs[buf][kk][col], &B[(size_t)(kt + kk) * ldb + col0 + col],
                 col0 + col < Nn);
        }
        CP_COMMIT();
    };

    float acc[2][8][4];
#pragma unroll
    for (int mt = 0; mt < 2; mt++)
#pragma unroll
        for (int nt = 0; nt < 8; nt++)
#pragma unroll
            for (int q = 0; q < 4; q++) acc[mt][nt][q] = 0.f;

    ld_tile(0, 0);
    CP_WAIT0();
    __syncthreads();

    const int T = Kk / BK;
    for (int t = 0; t < T; t++) {
        const int buf = t & 1;
        if (t + 1 < T) ld_tile((t + 1) * BK, buf ^ 1);

#pragma unroll
        for (int ks = 0; ks < 2; ks++) {
            const int k0 = ks * 8;
            unsigned a[2][4], b[8][2];
#pragma unroll
            for (int mt = 0; mt < 2; mt++) {
                int mr = wm0 + mt * 16;
                a[mt][0] = tf32_of(As[buf][mr + gid    ][k0 + tig]);
                a[mt][1] = tf32_of(As[buf][mr + gid + 8][k0 + tig]);
                a[mt][2] = tf32_of(As[buf][mr + gid    ][k0 + tig + 4]);
                a[mt][3] = tf32_of(As[buf][mr + gid + 8][k0 + tig + 4]);
            }
#pragma unroll
            for (int nt = 0; nt < 8; nt++) {
                int nc = wn0 + nt * 8;
                b[nt][0] = tf32_of(Bs[buf][k0 + tig    ][nc + gid]);
                b[nt][1] = tf32_of(Bs[buf][k0 + tig + 4][nc + gid]);
            }
#pragma unroll
            for (int mt = 0; mt < 2; mt++)
#pragma unroll
                for (int nt = 0; nt < 8; nt++)
                    mma_tf32(acc[mt][nt], a[mt], b[nt]);
        }

        if (t + 1 < T) {
            CP_WAIT0();
            __syncthreads();
        }
    }

    // epilogue
#pragma unroll
    for (int mt = 0; mt < 2; mt++) {
        int r = row0 + wm0 + mt * 16 + gid;
#pragma unroll
        for (int nt = 0; nt < 8; nt++) {
            int c = col0 + wn0 + nt * 8 + tig * 2;
            if (c < Nn) {
                float v0 = acc[mt][nt][0], v1 = acc[mt][nt][1];
                float v2 = acc[mt][nt][2], v3 = acc[mt][nt][3];
                if (EPI == 1) {
                    v0 += bias[c];     v0 = (v0 > 20.f) ? v0 : log1pf(expf(v0));
                    v1 += bias[c + 1]; v1 = (v1 > 20.f) ? v1 : log1pf(expf(v1));
                    v2 += bias[c];     v2 = (v2 > 20.f) ? v2 : log1pf(expf(v2));
                    v3 += bias[c + 1]; v3 = (v3 > 20.f) ? v3 : log1pf(expf(v3));
                }
                C[(size_t)r * ldc + c]           = v0;
                C[(size_t)r * ldc + c + 1]       = v1;
                C[(size_t)(r + 8) * ldc + c]     = v2;
                C[(size_t)(r + 8) * ldc + c + 1] = v3;
            }
        }
    }
}

// ===== causal grouped conv (K=4 taps, 2 groups) as shifted TF32 GEMM ======
// out[r, co] = sum_k sum_ci h[r - 2*(3-k), grp*1024+ci] * Wc[(k*1024+ci), co]
// epilogue: u = silu(out + b_conv)
__global__ __launch_bounds__(256, 2)
void conv_silu_k(const float* __restrict__ h, const float* __restrict__ Wc,
                 const float* __restrict__ bconv, float* __restrict__ U)
{
    __shared__ float As[2][BM][AS_S];
    __shared__ float Bs[2][BK][BS_S];

    const int tid  = threadIdx.x;
    const int row0 = blockIdx.y * BM;
    const int col0 = blockIdx.x * BN;
    const int grp  = col0 >> 10;
    const int warp = tid >> 5;
    const int lane = tid & 31;
    const int gid  = lane >> 2;
    const int tig  = lane & 3;
    const int wm0  = (warp & 3) * 32;
    const int wn0  = (warp >> 2) * 64;

    auto ld_tile = [&](int kt, int buf) {
        const int k     = kt >> 10;           // tap (BK=16 never straddles taps)
        const int ci0   = kt & 1023;
        const int shift = 2 * (3 - k);
#pragma unroll
        for (int i = 0; i < 2; i++) {
            int s = tid + i * 256, m = s >> 2, j = (s & 3) << 2;
            int rs = row0 + m - shift;
            cp16(&As[buf][m][j],
                 &h[(size_t)max(rs, 0) * (2 * HH) + grp * 1024 + ci0 + j],
                 rs >= 0);
        }
#pragma unroll
        for (int i = 0; i < 2; i++) {
            int s = tid + i * 256, kk = s >> 5, col = (s & 31) << 2;
            cp16(&Bs[buf][kk][col], &Wc[(size_t)(kt + kk) * HH + col0 + col], true);
        }
        CP_COMMIT();
    };

    float acc[2][8][4];
#pragma unroll
    for (int mt = 0; mt < 2; mt++)
#pragma unroll
        for (int nt = 0; nt < 8; nt++)
#pragma unroll
            for (int q = 0; q < 4; q++) acc[mt][nt][q] = 0.f;

    ld_tile(0, 0);
    CP_WAIT0();
    __syncthreads();

    const int T = (KK * 1024) / BK;
    for (int t = 0; t < T; t++) {
        const int buf = t & 1;
        if (t + 1 < T) ld_tile((t + 1) * BK, buf ^ 1);

#pragma unroll
        for (int ks = 0; ks < 2; ks++) {
            const int k0 = ks * 8;
            unsigned a[2][4], b[8][2];
#pragma unroll
            for (int mt = 0; mt < 2; mt++) {
                int mr = wm0 + mt * 16;
                a[mt][0] = tf32_of(As[buf][mr + gid    ][k0 + tig]);
                a[mt][1] = tf32_of(As[buf][mr + gid + 8][k0 + tig]);
                a[mt][2] = tf32_of(As[buf][mr + gid    ][k0 + tig + 4]);
                a[mt][3] = tf32_of(As[buf][mr + gid + 8][k0 + tig + 4]);
            }
#pragma unroll
            for (int nt = 0; nt < 8; nt++) {
                int nc = wn0 + nt * 8;
                b[nt][0] = tf32_of(Bs[buf][k0 + tig    ][nc + gid]);
                b[nt][1] = tf32_of(Bs[buf][k0 + tig + 4][nc + gid]);
            }
#pragma unroll
            for (int mt = 0; mt < 2; mt++)
#pragma unroll
                for (int nt = 0; nt < 8; nt++)
                    mma_tf32(acc[mt][nt], a[mt], b[nt]);
        }

        if (t + 1 < T) {
            CP_WAIT0();
            __syncthreads();
        }
    }

#pragma unroll
    for (int mt = 0; mt < 2; mt++) {
        int r = row0 + wm0 + mt * 16 + gid;
#pragma unroll
        for (int nt = 0; nt < 8; nt++) {
            int c = col0 + wn0 + nt * 8 + tig * 2;
            float v0 = acc[mt][nt][0] + bconv[c];
            float v1 = acc[mt][nt][1] + bconv[c + 1];
            float v2 = acc[mt][nt][2] + bconv[c];
            float v3 = acc[mt][nt][3] + bconv[c + 1];
            U[(size_t)r * HH + c]           = v0 * sigmoid_f(v0);
            U[(size_t)r * HH + c + 1]       = v1 * sigmoid_f(v1);
            U[(size_t)(r + 8) * HH + c]     = v2 * sigmoid_f(v2);
            U[(size_t)(r + 8) * HH + c + 1] = v3 * sigmoid_f(v3);
        }
    }
}

// ---------------- selective scan + fused z = y * silu(res) ----------------
__global__ __launch_bounds__(256)
void scan_k(const float* __restrict__ delta, const float* __restrict__ u,
            const float* __restrict__ proj, const float* __restrict__ A_log,
            const float* __restrict__ D, const float* __restrict__ h,
            float* __restrict__ z)
{
    const int gtid = blockIdx.x * blockDim.x + threadIdx.x;
    const int warp = gtid >> 5;
    const int lane = threadIdx.x & 31;
    const int sub  = lane >> 4;
    const int n    = lane & 15;
    const int c    = warp * 2 + sub;
    const int hi   = c >> 1;
    const int b    = c & 1;

    const float A  = -expf(A_log[hi * NN + n]);
    const float Dh = D[hi];
    float s = 0.f;

    for (int t = 0; t < LL; t++) {
        const int r = t * BB + b;
        float dt = __ldg(&delta[(size_t)r * HH + hi]);
        dt = fminf(fmaxf(dt, 0.001f), 0.1f);
        const float uu = __ldg(&u[(size_t)r * HH + hi]);
        const float Bn = __ldg(&proj[(size_t)r * PROJC + n]);
        const float Cn = __ldg(&proj[(size_t)r * PROJC + NN + n]);

        s = __expf(dt * A) * s + (dt * uu) * Bn;

        float p = Cn * s;
        p += __shfl_xor_sync(0xffffffffu, p, 1);
        p += __shfl_xor_sync(0xffffffffu, p, 2);
        p += __shfl_xor_sync(0xffffffffu, p, 4);
        p += __shfl_xor_sync(0xffffffffu, p, 8);

        if (n == 0) {
            const float yv  = p + uu * Dh;
            const float res = __ldg(&h[(size_t)r * (2 * HH) + HH + hi]);
            z[(size_t)r * HH + hi] = yv * (res * sigmoid_f(res));
        }
    }
}

// ---------------- launch ---------------------------------------------------
extern "C" void kernel_launch(void* const* d_in, const int* in_sizes, int n_in,
                              void* d_out, int out_size)
{
    const float* x      = (const float*)d_in[0];
    const float* W_in   = (const float*)d_in[1];
    const float* W_conv = (const float*)d_in[2];
    const float* b_conv = (const float*)d_in[3];
    const float* A_log  = (const float*)d_in[4];
    const float* D      = (const float*)d_in[5];
    const float* W_ssm  = (const float*)d_in[6];
    const float* W_dt   = (const float*)d_in[7];
    const float* b_dt   = (const float*)d_in[8];
    const float* W_out  = (const float*)d_in[9];
    float* out = (float*)d_out;

    void* p;
    cudaGetSymbolAddress(&p, g_h);     float* hbuf  = (float*)p;
    cudaGetSymbolAddress(&p, g_u);     float* ubuf  = (float*)p;
    cudaGetSymbolAddress(&p, g_proj);  float* pbuf  = (float*)p;
    cudaGetSymbolAddress(&p, g_delta); float* dbuf  = (float*)p;
    cudaGetSymbolAddress(&p, g_z);     float* zbuf  = (float*)p;

    dim3 blk(256);

    // 1) h = x @ W_in : (2048,1024)@(1024,4096)
    gemm_k<0><<<dim3(2 * HH / BN, MROWS / BM), blk>>>(
        x, FF, W_in, 2 * HH, hbuf, 2 * HH, 2 * HH, FF, nullptr);

    // 2) u = silu(causal grouped conv(xs) + b_conv)
    conv_silu_k<<<dim3(HH / BN, MROWS / BM), blk>>>(hbuf, W_conv, b_conv, ubuf);

    // 3) proj = u @ W_ssm : (2048,2048)@(2048,96)
    gemm_k<0><<<dim3(1, MROWS / BM), blk>>>(
        ubuf, HH, W_ssm, PROJC, pbuf, PROJC, PROJC, HH, nullptr);

    // 4) delta = softplus(proj[:,32:96] @ W_dt + b_dt) : (2048,64)@(64,2048)
    gemm_k<1><<<dim3(HH / BN, MROWS / BM), blk>>>(
        pbuf + 2 * NN, PROJC, W_dt, HH, dbuf, HH, HH, RR, b_dt);

    // 5) selective scan + z = y * silu(res): 4096 chains * 16 lanes
    scan_k<<<BB * HH * NN / 256, blk>>>(dbuf, ubuf, pbuf, A_log, D, hbuf, zbuf);

    // 6) out = z @ W_out : (2048,2048)@(2048,1024)
    gemm_k<0><<<dim3(FF / BN, MROWS / BM), blk>>>(
        zbuf, HH, W_out, FF, out, FF, FF, HH, nullptr);
}